// round 2
// baseline (speedup 1.0000x reference)
#include <cuda_runtime.h>
#include <math.h>

// Problem constants
#define BB 4
#define TT 4096
#define DD 1024
#define NC 128           // number of time chunks
#define LL (TT / NC)     // 32 timesteps per chunk
#define ROW (3 * DD)     // 3072 floats per (b,t)

// Scratch: per-chunk affine summaries and per-chunk initial states.
// Layout [chunk][b][d] so pass-2 per-channel walks are coalesced across threads.
__device__ float g_A[NC * BB * DD];
__device__ float g_S[NC * BB * DD];
__device__ float g_H[NC * BB * DD];

__device__ __forceinline__ float sigm(float v) {
    return 1.0f / (1.0f + __expf(-v));
}

// ---------------------------------------------------------------------------
// Pass 1: per-chunk summary. h_chunk_end = A * h_chunk_start + S.
// Reads only the inp and input-gate planes (2/3 of x).
// One block = (chunk c, batch b); 256 threads x float4 = all 1024 channels.
// ---------------------------------------------------------------------------
__global__ __launch_bounds__(256) void k_pass1(const float* __restrict__ x,
                                               const float* __restrict__ carry) {
    const int b = blockIdx.y;
    const int c = blockIdx.x;
    const int d = threadIdx.x * 4;

    const float* xb = x + (long)(b * TT + c * LL) * ROW + d;

    float A[4] = {1.f, 1.f, 1.f, 1.f};
    float S[4] = {0.f, 0.f, 0.f, 0.f};

#pragma unroll 4
    for (int t = 0; t < LL; t++) {
        float4 ip4 = *(const float4*)(xb + (long)t * ROW);
        float4 ig4 = *(const float4*)(xb + (long)t * ROW + DD);
        float ip[4] = {ip4.x, ip4.y, ip4.z, ip4.w};
        float ig[4] = {ig4.x, ig4.y, ig4.z, ig4.w};
#pragma unroll
        for (int j = 0; j < 4; j++) {
            float igs = sigm(ig[j]);
            float f   = 1.0f - igs;
            float sv  = tanhf(ip[j]) * igs;
            if (c == 0 && t == 0)
                sv += carry[b * DD + d + j] * f;
            A[j] = f * A[j];
            S[j] = f * S[j] + sv;
        }
    }

    const int idx = (c * BB + b) * DD + d;
    *(float4*)(&g_A[idx]) = make_float4(A[0], A[1], A[2], A[3]);
    *(float4*)(&g_S[idx]) = make_float4(S[0], S[1], S[2], S[3]);
}

// ---------------------------------------------------------------------------
// Pass 2: sequential scan over the NC chunk summaries per channel.
// Emits g_H[c] = h entering chunk c, and writes h_last into d_out[0 : B*D).
// Grid: BB blocks x 256 threads (float4 per thread).
// ---------------------------------------------------------------------------
__global__ __launch_bounds__(256) void k_pass2(float* __restrict__ out) {
    const int b = blockIdx.x;
    const int d = threadIdx.x * 4;

    float h[4] = {0.f, 0.f, 0.f, 0.f};
#pragma unroll 8
    for (int c = 0; c < NC; c++) {
        const int idx = (c * BB + b) * DD + d;
        *(float4*)(&g_H[idx]) = make_float4(h[0], h[1], h[2], h[3]);
        float4 A = *(const float4*)(&g_A[idx]);
        float4 S = *(const float4*)(&g_S[idx]);
        h[0] = A.x * h[0] + S.x;
        h[1] = A.y * h[1] + S.y;
        h[2] = A.z * h[2] + S.z;
        h[3] = A.w * h[3] + S.w;
    }
    // h_last
    *(float4*)(out + b * DD + d) = make_float4(h[0], h[1], h[2], h[3]);
}

// ---------------------------------------------------------------------------
// Pass 3: replay each chunk from its initial h; write y = tanh(h) * og.
// ---------------------------------------------------------------------------
__global__ __launch_bounds__(256) void k_pass3(const float* __restrict__ x,
                                               const float* __restrict__ carry,
                                               float* __restrict__ out) {
    const int b = blockIdx.y;
    const int c = blockIdx.x;
    const int d = threadIdx.x * 4;

    const float* xb = x + (long)(b * TT + c * LL) * ROW + d;
    float* yb = out + (long)BB * DD /* skip h_last */
                    + (long)(b * TT + c * LL) * DD + d;

    const int idx = (c * BB + b) * DD + d;
    float4 h4 = *(const float4*)(&g_H[idx]);
    float h[4] = {h4.x, h4.y, h4.z, h4.w};

#pragma unroll 4
    for (int t = 0; t < LL; t++) {
        float4 ip4 = *(const float4*)(xb + (long)t * ROW);
        float4 ig4 = *(const float4*)(xb + (long)t * ROW + DD);
        float4 og4 = *(const float4*)(xb + (long)t * ROW + 2 * DD);
        float ip[4] = {ip4.x, ip4.y, ip4.z, ip4.w};
        float ig[4] = {ig4.x, ig4.y, ig4.z, ig4.w};
        float og[4] = {og4.x, og4.y, og4.z, og4.w};
        float y[4];
#pragma unroll
        for (int j = 0; j < 4; j++) {
            float igs = sigm(ig[j]);
            float f   = 1.0f - igs;
            float sv  = tanhf(ip[j]) * igs;
            if (c == 0 && t == 0)
                sv += carry[b * DD + d + j] * f;
            h[j] = f * h[j] + sv;
            y[j] = tanhf(h[j]) * sigm(og[j]);
        }
        *(float4*)(yb + (long)t * DD) = make_float4(y[0], y[1], y[2], y[3]);
    }
}

extern "C" void kernel_launch(void* const* d_in, const int* in_sizes, int n_in,
                              void* d_out, int out_size) {
    const float* x     = (const float*)d_in[0];
    const float* carry = (const float*)d_in[1];
    float* out         = (float*)d_out;

    dim3 grid13(NC, BB);
    k_pass1<<<grid13, 256>>>(x, carry);
    k_pass2<<<BB, 256>>>(out);
    k_pass3<<<grid13, 256>>>(x, carry, out);
}